// round 5
// baseline (speedup 1.0000x reference)
#include <cuda_runtime.h>
#include <cstdint>

// Problem constants
#define BB 4
#define SS 2048
#define EE 1024
#define HH 16
#define DD 64
static constexpr int BHSD = BB * HH * SS * DD;   // 8388608 elements per tensor

// Scratch: q, k, v, values  (4 * 32MB = 128MB device-global, no allocation)
__device__ float g_scratch[4LL * BHSD];

// ---------------------------------------------------------------------------
// helpers
// ---------------------------------------------------------------------------
__device__ __forceinline__ uint32_t f2tf(float f) {
    uint32_t u;
    asm("cvt.rna.tf32.f32 %0, %1;" : "=r"(u) : "f"(f));
    return u;
}

__device__ __forceinline__ void mma_tf32(float c[4], const uint32_t a[4], const uint32_t b[2]) {
    asm volatile(
        "mma.sync.aligned.m16n8k8.row.col.f32.tf32.tf32.f32 "
        "{%0,%1,%2,%3}, {%4,%5,%6,%7}, {%8,%9}, {%0,%1,%2,%3};\n"
        : "+f"(c[0]), "+f"(c[1]), "+f"(c[2]), "+f"(c[3])
        : "r"(a[0]), "r"(a[1]), "r"(a[2]), "r"(a[3]), "r"(b[0]), "r"(b[1]));
}

__device__ __forceinline__ void cp16(uint32_t dst_smem, const void* src) {
    asm volatile("cp.async.cg.shared.global [%0], [%1], 16;\n" :: "r"(dst_smem), "l"(src));
}
#define CP_COMMIT()  asm volatile("cp.async.commit_group;\n")
#define CP_WAIT(n)   asm volatile("cp.async.wait_group %0;\n" :: "n"(n))

// ---------------------------------------------------------------------------
// GEMM: C[M,N] = A[M,K] @ B[K,N], fp32 in, tf32 MMA, fp32 accum.
// Block tile 128x128, K-tile 32, 256 threads (8 warps, each 64x32).
// EPI==0: plain row-major store to C.
// EPI==1: scatter into q/k/v head-major buffers (C = base of q; k,v follow).
// Shared pitches: A rows padded to 36 floats, B rows to 132 -> conflict-free frags.
// ---------------------------------------------------------------------------
static constexpr int AS_TILE = 128 * 36;   // floats per A buffer
static constexpr int BS_TILE = 32 * 132;   // floats per B buffer
static constexpr int GEMM_SMEM_FLOATS = 2 * AS_TILE + 2 * BS_TILE;

__device__ __forceinline__ void qkv_store(float* __restrict__ base, int r, int c, float v) {
    // r in [0, B*S), c in [0, 3*E)
    int b = r >> 11;            // /2048
    int s = r & 2047;
    int h = c / 192;
    int rem = c - h * 192;
    int which = rem >> 6;       // 0=q,1=k,2=v
    int d = rem & 63;
    base[(size_t)which * BHSD + ((((size_t)(b * HH + h)) * SS + s) << 6) + d] = v;
}

__device__ __forceinline__ void gemm_load_tile(
    const float* __restrict__ A, const float* __restrict__ Bm,
    int N, int K, int bm, int bn, int kt, int buf, uint32_t smb, int tid)
{
    const int aR = tid >> 3, aC = (tid & 7) * 4;
    const int bR = tid >> 5, bC = (tid & 31) * 4;
    const float* Ag = A + (size_t)bm * K + kt * 32;
#pragma unroll
    for (int i = 0; i < 4; i++) {
        int r = aR + i * 32;
        cp16(smb + (uint32_t)(buf * AS_TILE + r * 36 + aC) * 4, Ag + (size_t)r * K + aC);
    }
    const float* Bg = Bm + (size_t)kt * 32 * N + bn;
#pragma unroll
    for (int i = 0; i < 4; i++) {
        int r = bR + i * 8;
        cp16(smb + (uint32_t)(2 * AS_TILE + buf * BS_TILE + r * 132 + bC) * 4,
             Bg + (size_t)r * N + bC);
    }
    CP_COMMIT();
}

template <int EPI>
__global__ __launch_bounds__(256, 2)
void gemm_tf32(const float* __restrict__ A, const float* __restrict__ Bm,
               int N, int K, float* __restrict__ C)
{
    extern __shared__ float sm[];
    const int tid = threadIdx.x;
    const int lane = tid & 31, warp = tid >> 5;
    const int wm = warp >> 2, wn = warp & 3;     // 2 x 4 warp grid
    const int g = lane >> 2, t = lane & 3;
    const int bm = blockIdx.y * 128, bn = blockIdx.x * 128;
    const uint32_t smb = (uint32_t)__cvta_generic_to_shared(sm);

    float acc[4][4][4];
#pragma unroll
    for (int mt = 0; mt < 4; mt++)
#pragma unroll
        for (int nt = 0; nt < 4; nt++)
#pragma unroll
            for (int i = 0; i < 4; i++) acc[mt][nt][i] = 0.0f;

    const int NT = K >> 5;
    gemm_load_tile(A, Bm, N, K, bm, bn, 0, 0, smb, tid);

    for (int kt = 0; kt < NT; kt++) {
        if (kt + 1 < NT) {
            gemm_load_tile(A, Bm, N, K, bm, bn, kt + 1, (kt + 1) & 1, smb, tid);
            CP_WAIT(1);
        } else {
            CP_WAIT(0);
        }
        __syncthreads();

        const float* Ab = sm + (kt & 1) * AS_TILE;
        const float* Bb = sm + 2 * AS_TILE + (kt & 1) * BS_TILE;
#pragma unroll
        for (int ks = 0; ks < 4; ks++) {
            uint32_t af[4][4];
#pragma unroll
            for (int mt = 0; mt < 4; mt++) {
                int row = wm * 64 + mt * 16 + g;
                int col = ks * 8 + t;
                af[mt][0] = f2tf(Ab[row * 36 + col]);
                af[mt][1] = f2tf(Ab[(row + 8) * 36 + col]);
                af[mt][2] = f2tf(Ab[row * 36 + col + 4]);
                af[mt][3] = f2tf(Ab[(row + 8) * 36 + col + 4]);
            }
            uint32_t bf[4][2];
#pragma unroll
            for (int nt = 0; nt < 4; nt++) {
                int col = wn * 32 + nt * 8 + g;
                int row = ks * 8 + t;
                bf[nt][0] = f2tf(Bb[row * 132 + col]);
                bf[nt][1] = f2tf(Bb[(row + 4) * 132 + col]);
            }
#pragma unroll
            for (int mt = 0; mt < 4; mt++)
#pragma unroll
                for (int nt = 0; nt < 4; nt++)
                    mma_tf32(acc[mt][nt], af[mt], bf[nt]);
        }
        __syncthreads();
    }

    // epilogue
#pragma unroll
    for (int mt = 0; mt < 4; mt++) {
#pragma unroll
        for (int nt = 0; nt < 4; nt++) {
            int r = bm + wm * 64 + mt * 16 + g;
            int c = bn + wn * 32 + nt * 8 + 2 * t;
            if (EPI == 0) {
                C[(size_t)r * N + c]           = acc[mt][nt][0];
                C[(size_t)r * N + c + 1]       = acc[mt][nt][1];
                C[(size_t)(r + 8) * N + c]     = acc[mt][nt][2];
                C[(size_t)(r + 8) * N + c + 1] = acc[mt][nt][3];
            } else {
                qkv_store(C, r,     c,     acc[mt][nt][0]);
                qkv_store(C, r,     c + 1, acc[mt][nt][1]);
                qkv_store(C, r + 8, c,     acc[mt][nt][2]);
                qkv_store(C, r + 8, c + 1, acc[mt][nt][3]);
            }
        }
    }
}

// ---------------------------------------------------------------------------
// Flash attention: one CTA per (b,h, 64-query block). 128 threads, 4 warps.
// Each warp owns 16 query rows (full 64-key width per KV iteration).
// Shared: Qs,Ks,Vs,Ps each [64][68] floats (pitch 68 -> conflict-free frags).
// ---------------------------------------------------------------------------
static constexpr int ATT_PITCH = 68;
static constexpr int ATT_TILE = 64 * ATT_PITCH;
static constexpr int ATT_SMEM_FLOATS = 4 * ATT_TILE;

__global__ __launch_bounds__(128, 3)
void attn_kernel(const float* __restrict__ Q, const float* __restrict__ Kp,
                 const float* __restrict__ Vp, float* __restrict__ Out)
{
    extern __shared__ float sm[];
    float* Qs = sm;
    float* Ks = sm + ATT_TILE;
    float* Vs = sm + 2 * ATT_TILE;
    float* Ps = sm + 3 * ATT_TILE;

    const int tid = threadIdx.x, lane = tid & 31, warp = tid >> 5;
    const int g = lane >> 2, t = lane & 3;
    const int bh = blockIdx.y;             // b*H + h
    const int qb = blockIdx.x;             // query block (64 rows)
    const int b = bh >> 4, h = bh & 15;
    const float* Qg = Q + (size_t)bh * SS * DD + (size_t)qb * 64 * DD;
    const float* Kg = Kp + (size_t)bh * SS * DD;
    const float* Vg = Vp + (size_t)bh * SS * DD;
    const uint32_t smb = (uint32_t)__cvta_generic_to_shared(sm);
    const int qrow = warp * 16;

    // async-load Q tile (64x64)
    {
        int c4 = (tid & 15) * 4, r0 = tid >> 4;
#pragma unroll
        for (int i = 0; i < 8; i++) {
            int r = r0 + i * 8;
            cp16(smb + (uint32_t)(r * ATT_PITCH + c4) * 4, Qg + r * DD + c4);
        }
        CP_COMMIT();
    }

    float m0 = -3.0e38f, m1 = -3.0e38f, l0 = 0.0f, l1 = 0.0f;
    float o[8][4];
#pragma unroll
    for (int nt = 0; nt < 8; nt++)
#pragma unroll
        for (int i = 0; i < 4; i++) o[nt][i] = 0.0f;

    for (int j = 0; j < 32; j++) {
        __syncthreads();   // all warps done with previous Ks/Vs
        {
            int c4 = (tid & 15) * 4, r0 = tid >> 4;
            const float* Kt = Kg + (size_t)j * 64 * DD;
            const float* Vt = Vg + (size_t)j * 64 * DD;
#pragma unroll
            for (int i = 0; i < 8; i++) {
                int r = r0 + i * 8;
                cp16(smb + (uint32_t)(ATT_TILE + r * ATT_PITCH + c4) * 4, Kt + r * DD + c4);
            }
#pragma unroll
            for (int i = 0; i < 8; i++) {
                int r = r0 + i * 8;
                cp16(smb + (uint32_t)(2 * ATT_TILE + r * ATT_PITCH + c4) * 4, Vt + r * DD + c4);
            }
            CP_COMMIT();
            CP_WAIT(0);
        }
        __syncthreads();

        // S = Q @ K^T  (per warp: 16 rows x 64 keys, k-dim = 64)
        float s[8][4];
#pragma unroll
        for (int nt = 0; nt < 8; nt++)
#pragma unroll
            for (int i = 0; i < 4; i++) s[nt][i] = 0.0f;

#pragma unroll
        for (int ks = 0; ks < 8; ks++) {
            uint32_t af[4];
            int ro = qrow + g, co = ks * 8 + t;
            af[0] = f2tf(Qs[ro * ATT_PITCH + co]);
            af[1] = f2tf(Qs[(ro + 8) * ATT_PITCH + co]);
            af[2] = f2tf(Qs[ro * ATT_PITCH + co + 4]);
            af[3] = f2tf(Qs[(ro + 8) * ATT_PITCH + co + 4]);
#pragma unroll
            for (int nt = 0; nt < 8; nt++) {
                uint32_t bf[2];
                int kc = nt * 8 + g;                      // key index
                bf[0] = f2tf(Ks[kc * ATT_PITCH + co]);    // K[key][dh]
                bf[1] = f2tf(Ks[kc * ATT_PITCH + co + 4]);
                mma_tf32(s[nt], af, bf);
            }
        }

        // scale + online softmax (rows g, g+8 of this warp's 16)
        float rmax0 = -3.0e38f, rmax1 = -3.0e38f;
#pragma unroll
        for (int nt = 0; nt < 8; nt++) {
#pragma unroll
            for (int i = 0; i < 4; i++) s[nt][i] *= 0.125f;
            rmax0 = fmaxf(rmax0, fmaxf(s[nt][0], s[nt][1]));
            rmax1 = fmaxf(rmax1, fmaxf(s[nt][2], s[nt][3]));
        }
        rmax0 = fmaxf(rmax0, __shfl_xor_sync(0xffffffffu, rmax0, 1));
        rmax0 = fmaxf(rmax0, __shfl_xor_sync(0xffffffffu, rmax0, 2));
        rmax1 = fmaxf(rmax1, __shfl_xor_sync(0xffffffffu, rmax1, 1));
        rmax1 = fmaxf(rmax1, __shfl_xor_sync(0xffffffffu, rmax1, 2));

        float mn0 = fmaxf(m0, rmax0), mn1 = fmaxf(m1, rmax1);
        float a0 = __expf(m0 - mn0), a1 = __expf(m1 - mn1);
        m0 = mn0; m1 = mn1;

        float rs0 = 0.0f, rs1 = 0.0f;
#pragma unroll
        for (int nt = 0; nt < 8; nt++) {
            s[nt][0] = __expf(s[nt][0] - mn0);
            s[nt][1] = __expf(s[nt][1] - mn0);
            s[nt][2] = __expf(s[nt][2] - mn1);
            s[nt][3] = __expf(s[nt][3] - mn1);
            rs0 += s[nt][0] + s[nt][1];
            rs1 += s[nt][2] + s[nt][3];
        }
        rs0 += __shfl_xor_sync(0xffffffffu, rs0, 1);
        rs0 += __shfl_xor_sync(0xffffffffu, rs0, 2);
        rs1 += __shfl_xor_sync(0xffffffffu, rs1, 1);
        rs1 += __shfl_xor_sync(0xffffffffu, rs1, 2);
        l0 = l0 * a0 + rs0;
        l1 = l1 * a1 + rs1;

        // rescale O accumulators
#pragma unroll
        for (int nt = 0; nt < 8; nt++) {
            o[nt][0] *= a0; o[nt][1] *= a0;
            o[nt][2] *= a1; o[nt][3] *= a1;
        }

        // stage P to (warp-private rows of) shared
#pragma unroll
        for (int nt = 0; nt < 8; nt++) {
            int r = qrow + g, c = nt * 8 + 2 * t;
            Ps[r * ATT_PITCH + c]           = s[nt][0];
            Ps[r * ATT_PITCH + c + 1]       = s[nt][1];
            Ps[(r + 8) * ATT_PITCH + c]     = s[nt][2];
            Ps[(r + 8) * ATT_PITCH + c + 1] = s[nt][3];
        }
        __syncwarp();

        // O += P @ V   (k-dim = keys 64, n = dh 64)
#pragma unroll
        for (int ks = 0; ks < 8; ks++) {
            uint32_t af[4];
            int ro = qrow + g, co = ks * 8 + t;          // co = key index
            af[0] = f2tf(Ps[ro * ATT_PITCH + co]);
            af[1] = f2tf(Ps[(ro + 8) * ATT_PITCH + co]);
            af[2] = f2tf(Ps[ro * ATT_PITCH + co + 4]);
            af[3] = f2tf(Ps[(ro + 8) * ATT_PITCH + co + 4]);
#pragma unroll
            for (int nt = 0; nt < 8; nt++) {
                uint32_t bf[2];
                int vc = nt * 8 + g;                      // dh col
                bf[0] = f2tf(Vs[co * ATT_PITCH + vc]);    // V[key][dh]
                bf[1] = f2tf(Vs[(co + 4) * ATT_PITCH + vc]);
                mma_tf32(o[nt], af, bf);
            }
        }
        __syncwarp();   // Ps reads done before next iteration overwrites
    }

    // epilogue: normalize and write into values[b][s][h*64+d]
    float i0 = 1.0f / l0, i1 = 1.0f / l1;
#pragma unroll
    for (int nt = 0; nt < 8; nt++) {
        int srow = qb * 64 + qrow + g;
        int d = nt * 8 + 2 * t;
        size_t base0 = ((size_t)(b * SS + srow)) * EE + h * DD + d;
        size_t base1 = ((size_t)(b * SS + srow + 8)) * EE + h * DD + d;
        Out[base0]     = o[nt][0] * i0;
        Out[base0 + 1] = o[nt][1] * i0;
        Out[base1]     = o[nt][2] * i1;
        Out[base1 + 1] = o[nt][3] * i1;
    }
}

// ---------------------------------------------------------------------------
// launch
// ---------------------------------------------------------------------------
extern "C" void kernel_launch(void* const* d_in, const int* in_sizes, int n_in,
                              void* d_out, int out_size)
{
    const float* x    = (const float*)d_in[0];   // [4,2048,1024]
    const float* Wqkv = (const float*)d_in[1];   // [1024,3072]
    const float* Wout = (const float*)d_in[2];   // [1024,1024]
    float* out = (float*)d_out;                  // [4,2048,1024]

    float* scratch = nullptr;
    cudaGetSymbolAddress((void**)&scratch, g_scratch);
    float* q   = scratch;                 // qkv_store indexes k,v from this base
    float* k   = scratch + (size_t)BHSD;
    float* v   = scratch + (size_t)2 * BHSD;
    float* val = scratch + (size_t)3 * BHSD;

    const int smemG = GEMM_SMEM_FLOATS * 4;   // 70656 B
    const int smemA = ATT_SMEM_FLOATS * 4;    // 69632 B
    cudaFuncSetAttribute(gemm_tf32<1>, cudaFuncAttributeMaxDynamicSharedMemorySize, smemG);
    cudaFuncSetAttribute(gemm_tf32<0>, cudaFuncAttributeMaxDynamicSharedMemorySize, smemG);
    cudaFuncSetAttribute(attn_kernel,  cudaFuncAttributeMaxDynamicSharedMemorySize, smemA);

    // 1) QKV projection, scattered into head-major q/k/v
    gemm_tf32<1><<<dim3(3 * EE / 128, BB * SS / 128), 256, smemG>>>(x, Wqkv, 3 * EE, EE, q);
    // 2) flash attention -> values in [B,S,E] layout
    attn_kernel<<<dim3(SS / 64, BB * HH), 128, smemA>>>(q, k, v, val);
    // 3) output projection
    gemm_tf32<0><<<dim3(EE / 128, BB * SS / 128), 256, smemG>>>(val, Wout, EE, EE, out);
}